// round 17
// baseline (speedup 1.0000x reference)
#include <cuda_runtime.h>
#include <cuda_fp16.h>
#include <cstdint>
#include <math.h>

#define BATCH   32
#define CHUNK   480000
#define NFFT    400
#define HOP     160
#define NMELS   128
#define NFREQ   201
#define NFRAMES 3000
#define NFRTOT  (BATCH * NFRAMES)   // 96000
#define KP      208                 // padded half-K (200 real + 8 zero)
#define NT      128                 // frames per B tile
#define NNT     (NFRTOT / NT)       // 750
#define ASTR    432                 // smem row stride bytes (208 fp16 = 416B + 16 pad)
#define MR      224                 // M rows per block (covers 202 real + pad)
#define A_BYTES (MR * ASTR)         // 96768
#define B_BYTES (128 * ASTR)        // 55296 per buffer
#define SMEMSZ  (A_BYTES + 2 * B_BYTES)   // 207360
#define MLIM_E  202                 // even-class real rows (k=0,2,...,200)
#define MLIM_O  200                 // odd-class real rows  (k=1,3,...,199)
#define NKS     13                  // k16 steps (208 / 16)
#define NGR     26                  // 16B granules per 416B row
#define NSMB    148                 // grid x (persistent slots)
#define STH     512                 // stft threads

// ---------------- device scratch ------------------------------------------------
__device__ __align__(16) __half g_powh[(size_t)NFREQ * NFRTOT];   // fp16 power, 38.5 MB
__device__ __align__(16) __half g_u[(size_t)NFRTOT * KP];         // even-class B, 40 MB
__device__ __align__(16) __half g_v[(size_t)NFRTOT * KP];         // odd-class B, 40 MB
__device__ __align__(16) __half g_ae[256 * KP];                   // even basis
__device__ __align__(16) __half g_ao[256 * KP];                   // odd basis
__device__ unsigned g_max[BATCH];
__device__ int g_flo[NMELS];
__device__ int g_fhi[NMELS];

// ---------------- helpers -------------------------------------------------------
__device__ __forceinline__ uint32_t smem_u32(const void* p) {
    uint32_t a;
    asm("{ .reg .u64 t; cvta.to.shared.u64 t, %1; cvt.u32.u64 %0, t; }" : "=r"(a) : "l"(p));
    return a;
}
__device__ __forceinline__ void cp16(uint32_t saddr, const void* gaddr) {
    asm volatile("cp.async.cg.shared.global [%0], [%1], 16;" :: "r"(saddr), "l"(gaddr) : "memory");
}
__device__ __forceinline__ void ldsm_x4(uint32_t& r0, uint32_t& r1, uint32_t& r2, uint32_t& r3,
                                        uint32_t addr) {
    asm volatile("ldmatrix.sync.aligned.m8n8.x4.shared.b16 {%0,%1,%2,%3}, [%4];"
                 : "=r"(r0), "=r"(r1), "=r"(r2), "=r"(r3) : "r"(addr));
}
__device__ __forceinline__ void mma16816(float* d, const uint32_t* a, uint32_t b0, uint32_t b1) {
    asm volatile("mma.sync.aligned.m16n8k16.row.col.f32.f16.f16.f32 "
                 "{%0,%1,%2,%3}, {%4,%5,%6,%7}, {%8,%9}, {%0,%1,%2,%3};"
                 : "+f"(d[0]), "+f"(d[1]), "+f"(d[2]), "+f"(d[3])
                 : "r"(a[0]), "r"(a[1]), "r"(a[2]), "r"(a[3]), "r"(b0), "r"(b1));
}
__device__ __forceinline__ unsigned f2ord(float f) {
    unsigned u = __float_as_uint(f);
    return (u & 0x80000000u) ? ~u : (u | 0x80000000u);
}
__device__ __forceinline__ float ord2f(unsigned u) {
    return __uint_as_float((u & 0x80000000u) ? (u & 0x7fffffffu) : ~u);
}

// ---------------- prep: basis tables (fp64), mel ranges, maxes ------------------
__global__ void prep_kernel(const float* __restrict__ fb) {
    const int idx = blockIdx.x * blockDim.x + threadIdx.x;
    const int stride = gridDim.x * blockDim.x;
    const int total = 2 * 256 * KP;
    for (int e = idx; e < total; e += stride) {
        int tab = e / (256 * KP);
        int rem = e - tab * (256 * KP);
        int R = rem / KP;
        int r = rem - R * KP;
        int mlim = tab ? MLIM_O : MLIM_E;
        __half v = __float2half_rn(0.0f);
        if (R < mlim && r < 200) {
            int k = 2 * (R >> 1) + tab;
            double ang = (2.0 * M_PI / 400.0) * (double)k * (double)r;
            double bv = (R & 1) ? -sin(ang) : cos(ang);
            v = __float2half_rn((float)bv);
        }
        (tab ? g_ao : g_ae)[R * KP + r] = v;
    }
    if (idx < NMELS) {
        int lo = NFREQ, hi = 0;
        for (int f = 0; f < NFREQ; ++f) {
            if (fb[idx * NFREQ + f] != 0.0f) { if (f < lo) lo = f; hi = f + 1; }
        }
        if (lo >= hi) { lo = 0; hi = 0; }
        g_flo[idx] = lo;
        g_fhi[idx] = hi;
    }
    if (idx < BATCH) g_max[idx] = f2ord(-3.0e38f);
}

// ---------------- prep: radix-2 folded inputs u,v (8-wide) ----------------------
// grid (375, 32), 208 threads: thread -> (frame fl = tid/26, octet q = tid%26).
// Interior frames: 2x float4 loads per operand, one uint4 store per array.
// Edge frames (t = 0, 1, 2999): scalar reflect. q == 25 -> zero padding.
__global__ void __launch_bounds__(208) prep_uv(const float* __restrict__ audio,
                                               const float* __restrict__ cosk) {
    const int tid = threadIdx.x;
    const int fl = tid / 26;
    const int q = tid - fl * 26;
    const int t = blockIdx.x * 8 + fl;
    const int b = blockIdx.y;
    const int r0 = 8 * q;
    const size_t o = ((size_t)b * NFRAMES + t) * KP + r0;
    uint4* du = reinterpret_cast<uint4*>(g_u + o);
    uint4* dv = reinterpret_cast<uint4*>(g_v + o);
    if (q == 25) {                       // r in [200, 208): zero pad
        *du = make_uint4(0u, 0u, 0u, 0u);
        *dv = make_uint4(0u, 0u, 0u, 0u);
        return;
    }
    const float* ap = audio + (size_t)b * CHUNK;
    float x1[8], x2[8];
    if (t >= 2 && t <= 2998) {
        const float4* s1 = reinterpret_cast<const float4*>(ap + (t * HOP - 200 + r0));
        const float4* s2 = reinterpret_cast<const float4*>(ap + (t * HOP + r0));
        const float4 a1 = s1[0], b1 = s1[1];
        const float4 a2 = s2[0], b2 = s2[1];
        x1[0] = a1.x; x1[1] = a1.y; x1[2] = a1.z; x1[3] = a1.w;
        x1[4] = b1.x; x1[5] = b1.y; x1[6] = b1.z; x1[7] = b1.w;
        x2[0] = a2.x; x2[1] = a2.y; x2[2] = a2.z; x2[3] = a2.w;
        x2[4] = b2.x; x2[5] = b2.y; x2[6] = b2.z; x2[7] = b2.w;
    } else {
#pragma unroll
        for (int j = 0; j < 8; ++j) {
            int s = t * HOP - 200 + r0 + j;
            if (s < 0) s = -s;
            int s2 = t * HOP + r0 + j;
            if (s2 >= CHUNK) s2 = 2 * CHUNK - 2 - s2;
            x1[j] = ap[s];
            x2[j] = ap[s2];
        }
    }
    const float4* wp = reinterpret_cast<const float4*>(cosk + r0);
    const float4* wq = reinterpret_cast<const float4*>(cosk + 200 + r0);
    const float4 w0 = wp[0], w1 = wp[1];
    const float4 w2 = wq[0], w3 = wq[1];
    const float wa[8] = {w0.x, w0.y, w0.z, w0.w, w1.x, w1.y, w1.z, w1.w};
    const float wb[8] = {w2.x, w2.y, w2.z, w2.w, w3.x, w3.y, w3.z, w3.w};
    __half uh[8], vh[8];
#pragma unroll
    for (int j = 0; j < 8; ++j) {
        uh[j] = __float2half_rn(fmaf(wa[j], x1[j],  wb[j] * x2[j]));
        vh[j] = __float2half_rn(fmaf(wa[j], x1[j], -wb[j] * x2[j]));
    }
    *du = *reinterpret_cast<uint4*>(uh);
    *dv = *reinterpret_cast<uint4*>(vh);
}

// ---------------- STFT: persistent-A radix-2 fp16 mma.sync (512 thr) ------------
// grid (148, 2): y = class. Whole-class A (224 x 208) resident; B double-buffered.
// 16 warps: 2m x 8n, warp tile 112M x 16N (MI=7, NI=2).
// wm==1, mi==6 covers rows 208..223 (all padding) -> uniformly skipped.
__global__ void __launch_bounds__(STH, 1) stft_mma_kernel() {
    extern __shared__ __align__(128) char smem[];
    const int tid = threadIdx.x;
    const int lane = tid & 31;
    const int warp = tid >> 5;       // 0..15
    const int wm = warp >> 3;        // 0..1
    const int wn = warp & 7;         // 0..7
    const int bx = blockIdx.x;
    const int cls = blockIdx.y;
    const int mlim = cls ? MLIM_O : MLIM_E;
    const __half* Atab = cls ? g_ao : g_ae;
    const __half* Btab = cls ? g_v : g_u;
    const int nit = (NNT - bx + NSMB - 1) / NSMB;
    const int milim = (wm == 1) ? 6 : 7;   // skip all-padding m-tile

    // ---- load A (once): 224 rows x 26 granules ----
    for (int g = tid; g < MR * NGR; g += STH) {
        const int row = g / NGR;
        const int gi = g - row * NGR;
        cp16(smem_u32(smem + row * ASTR + gi * 16), Atab + (size_t)row * KP + gi * 8);
    }
    // ---- load B for first ntile into buffer 0 ----
    for (int g = tid; g < NT * NGR; g += STH) {
        const int row = g / NGR;
        const int gi = g - row * NGR;
        cp16(smem_u32(smem + A_BYTES + row * ASTR + gi * 16),
             Btab + (size_t)(bx * NT + row) * KP + gi * 8);
    }
    asm volatile("cp.async.commit_group;" ::: "memory");

    const uint32_t sbase32 = smem_u32(smem);
    const uint32_t aAddrOff = (uint32_t)((wm * 112 + (lane & 15)) * ASTR + ((lane >> 4) << 4));
    const uint32_t bAddrOff = (uint32_t)((wn * 16 + (lane & 7) + ((lane >> 4) << 3)) * ASTR
                                         + (((lane >> 3) & 1) << 4));
    const int r = lane >> 2;
    const bool evenr = (r & 1) == 0;

    for (int it = 0; it < nit; ++it) {
        const int ntile = bx + NSMB * it;
        if (it + 1 < nit) {
            const int ntn = bx + NSMB * (it + 1);
            char* bbuf = smem + A_BYTES + ((it + 1) & 1) * B_BYTES;
            for (int g = tid; g < NT * NGR; g += STH) {
                const int row = g / NGR;
                const int gi = g - row * NGR;
                cp16(smem_u32(bbuf + row * ASTR + gi * 16),
                     Btab + (size_t)(ntn * NT + row) * KP + gi * 8);
            }
            asm volatile("cp.async.commit_group;" ::: "memory");
            asm volatile("cp.async.wait_group 1;" ::: "memory");
        } else {
            asm volatile("cp.async.wait_group 0;" ::: "memory");
        }
        __syncthreads();

        float acc[7][2][4];
#pragma unroll
        for (int mi = 0; mi < 7; ++mi)
#pragma unroll
            for (int ni = 0; ni < 2; ++ni)
#pragma unroll
                for (int qq = 0; qq < 4; ++qq) acc[mi][ni][qq] = 0.0f;

        const uint32_t aA = sbase32;
        const uint32_t aB = sbase32 + (uint32_t)(A_BYTES + (it & 1) * B_BYTES);
#pragma unroll
        for (int ks = 0; ks < NKS; ++ks) {
            const uint32_t kb = (uint32_t)(ks * 32);
            uint32_t ah[7][4], bq[2][2];
#pragma unroll
            for (int mi = 0; mi < 7; ++mi)
                if (mi < milim)
                    ldsm_x4(ah[mi][0], ah[mi][1], ah[mi][2], ah[mi][3],
                            aA + aAddrOff + (uint32_t)(mi * 16 * ASTR) + kb);
            ldsm_x4(bq[0][0], bq[0][1], bq[1][0], bq[1][1], aB + bAddrOff + kb);
#pragma unroll
            for (int mi = 0; mi < 7; ++mi)
                if (mi < milim)
#pragma unroll
                    for (int ni = 0; ni < 2; ++ni)
                        mma16816(acc[mi][ni], ah[mi], bq[ni][0], bq[ni][1]);
        }

        // ---- epilogue: power = re^2 + im^2 (row pairs lane^4), fp16 stores ------
#pragma unroll
        for (int mi = 0; mi < 7; ++mi) {
            if (mi >= milim) continue;
#pragma unroll
            for (int ni = 0; ni < 2; ++ni) {
                float p0 = acc[mi][ni][0] * acc[mi][ni][0];
                float p1 = acc[mi][ni][1] * acc[mi][ni][1];
                float p2 = acc[mi][ni][2] * acc[mi][ni][2];
                float p3 = acc[mi][ni][3] * acc[mi][ni][3];
                p0 += __shfl_xor_sync(0xffffffffu, p0, 4);
                p1 += __shfl_xor_sync(0xffffffffu, p1, 4);
                p2 += __shfl_xor_sync(0xffffffffu, p2, 4);
                p3 += __shfl_xor_sync(0xffffffffu, p3, 4);
                if (evenr) {
                    const int fr = ntile * NT + wn * 16 + ni * 8 + 2 * (lane & 3);
                    const int R0 = wm * 112 + mi * 16 + r;
                    if (R0 < mlim) {
                        const int f = 2 * (R0 >> 1) + cls;
                        __half2* dst = reinterpret_cast<__half2*>(g_powh + (size_t)f * NFRTOT + fr);
                        *dst = __floats2half2_rn(p0, p1);
                    }
                    const int R1 = R0 + 8;
                    if (R1 < mlim) {
                        const int f = 2 * (R1 >> 1) + cls;
                        __half2* dst = reinterpret_cast<__half2*>(g_powh + (size_t)f * NFRTOT + fr);
                        *dst = __floats2half2_rn(p2, p3);
                    }
                }
            }
        }
        __syncthreads();   // protect next iteration's B buffer overwrite
    }
}

// ---------------- mel: one thread per (batch, mel, 2x8 frames) ------------------
// grid (1, 128, 32), 192 threads; thread q owns 8-frame groups 2q and 2q+1 —
// two independent uint4 load chains interleaved in the f loop for ILP.
__global__ void __launch_bounds__(192) mel_kernel(const float* __restrict__ fb,
                                                  float* __restrict__ out) {
    const int q = threadIdx.x;           // 0..191
    const int m = blockIdx.y;
    const int b = blockIdx.z;
    float lmax = -3.0e38f;
    const int g0 = 2 * q;
    const int g1 = 2 * q + 1;
    if (g0 < NFRAMES / 8) {
        const bool has1 = (g1 < NFRAMES / 8);
        const int t0 = g0 * 8;
        const int t1 = (has1 ? g1 : g0) * 8;
        const int lo = g_flo[m];
        const int hi = g_fhi[m];
        const float* fbm = fb + m * NFREQ;
        const __half* base = g_powh + (size_t)lo * NFRTOT + (size_t)b * NFRAMES;
        const uint4* p0 = reinterpret_cast<const uint4*>(base + t0);
        const uint4* p1 = reinterpret_cast<const uint4*>(base + t1);
        const size_t stride16 = NFRTOT / 8;
        float a0[8], a1[8];
#pragma unroll
        for (int j = 0; j < 8; ++j) { a0[j] = 0.0f; a1[j] = 0.0f; }
        for (int f = lo; f < hi; ++f) {
            const float w = __ldg(&fbm[f]);
            uint4 r0 = *p0; p0 += stride16;
            uint4 r1 = *p1; p1 += stride16;
            const float2 u01 = __half22float2(*reinterpret_cast<const __half2*>(&r0.x));
            const float2 u23 = __half22float2(*reinterpret_cast<const __half2*>(&r0.y));
            const float2 u45 = __half22float2(*reinterpret_cast<const __half2*>(&r0.z));
            const float2 u67 = __half22float2(*reinterpret_cast<const __half2*>(&r0.w));
            const float2 v01 = __half22float2(*reinterpret_cast<const __half2*>(&r1.x));
            const float2 v23 = __half22float2(*reinterpret_cast<const __half2*>(&r1.y));
            const float2 v45 = __half22float2(*reinterpret_cast<const __half2*>(&r1.z));
            const float2 v67 = __half22float2(*reinterpret_cast<const __half2*>(&r1.w));
            a0[0] = fmaf(w, u01.x, a0[0]); a0[1] = fmaf(w, u01.y, a0[1]);
            a0[2] = fmaf(w, u23.x, a0[2]); a0[3] = fmaf(w, u23.y, a0[3]);
            a0[4] = fmaf(w, u45.x, a0[4]); a0[5] = fmaf(w, u45.y, a0[5]);
            a0[6] = fmaf(w, u67.x, a0[6]); a0[7] = fmaf(w, u67.y, a0[7]);
            a1[0] = fmaf(w, v01.x, a1[0]); a1[1] = fmaf(w, v01.y, a1[1]);
            a1[2] = fmaf(w, v23.x, a1[2]); a1[3] = fmaf(w, v23.y, a1[3]);
            a1[4] = fmaf(w, v45.x, a1[4]); a1[5] = fmaf(w, v45.y, a1[5]);
            a1[6] = fmaf(w, v67.x, a1[6]); a1[7] = fmaf(w, v67.y, a1[7]);
        }
        float* op = out + ((size_t)b * NMELS + m) * NFRAMES;
        float r0[8];
#pragma unroll
        for (int j = 0; j < 8; ++j) {
            r0[j] = __log10f(fmaxf(a0[j], 1e-10f));
            lmax = fmaxf(lmax, r0[j]);
        }
        float4* o0 = reinterpret_cast<float4*>(op + t0);
        o0[0] = make_float4(r0[0], r0[1], r0[2], r0[3]);
        o0[1] = make_float4(r0[4], r0[5], r0[6], r0[7]);
        if (has1) {
            float r1[8];
#pragma unroll
            for (int j = 0; j < 8; ++j) {
                r1[j] = __log10f(fmaxf(a1[j], 1e-10f));
                lmax = fmaxf(lmax, r1[j]);
            }
            float4* o1 = reinterpret_cast<float4*>(op + t1);
            o1[0] = make_float4(r1[0], r1[1], r1[2], r1[3]);
            o1[1] = make_float4(r1[4], r1[5], r1[6], r1[7]);
        }
    }
    __shared__ float wmax[8];
#pragma unroll
    for (int o = 16; o; o >>= 1)
        lmax = fmaxf(lmax, __shfl_xor_sync(0xffffffffu, lmax, o));
    if ((threadIdx.x & 31) == 0) wmax[threadIdx.x >> 5] = lmax;
    __syncthreads();
    if (threadIdx.x < 8) {
        float v = (threadIdx.x < 6) ? wmax[threadIdx.x] : -3.0e38f;
#pragma unroll
        for (int o = 4; o; o >>= 1)
            v = fmaxf(v, __shfl_xor_sync(0xffu, v, o));
        if (threadIdx.x == 0) atomicMax(&g_max[b], f2ord(v));
    }
}

// ---------------- finalize: floor at max-8, normalize (2 float4 / thread) -------
__global__ void __launch_bounds__(256) fin_kernel(float* __restrict__ out) {
    const int b = blockIdx.y;
    const float floorv = ord2f(g_max[b]) - 8.0f;
    const size_t base = 2 * ((size_t)blockIdx.x * blockDim.x + threadIdx.x);
    const size_t per = (size_t)NMELS * NFRAMES / 4;
    float4* pb = reinterpret_cast<float4*>(out + (size_t)b * NMELS * NFRAMES);
#pragma unroll
    for (int j = 0; j < 2; ++j) {
        const size_t idx = base + j;
        if (idx < per) {
            float4 v = pb[idx];
            v.x = (fmaxf(v.x, floorv) + 4.0f) * 0.25f;
            v.y = (fmaxf(v.y, floorv) + 4.0f) * 0.25f;
            v.z = (fmaxf(v.z, floorv) + 4.0f) * 0.25f;
            v.w = (fmaxf(v.w, floorv) + 4.0f) * 0.25f;
            pb[idx] = v;
        }
    }
}

// ---------------- launch --------------------------------------------------------
extern "C" void kernel_launch(void* const* d_in, const int* in_sizes, int n_in,
                              void* d_out, int out_size) {
    const float* audio = (const float*)d_in[0];
    const float* cosk  = (const float*)d_in[1];
    const float* fb    = (const float*)d_in[3];
    float* out = (float*)d_out;

    cudaFuncSetAttribute(stft_mma_kernel, cudaFuncAttributeMaxDynamicSharedMemorySize, SMEMSZ);

    prep_kernel<<<1024, 256>>>(fb);
    prep_uv<<<dim3(NFRAMES / 8, BATCH), 208>>>(audio, cosk);

    stft_mma_kernel<<<dim3(NSMB, 2), STH, SMEMSZ>>>();

    dim3 gm(1, NMELS, BATCH);                                 // (1, 128, 32)
    mel_kernel<<<gm, 192>>>(fb, out);

    dim3 gf((NMELS * NFRAMES / 8 + 255) / 256, BATCH);
    fin_kernel<<<gf, 256>>>(out);
}